// round 16
// baseline (speedup 1.0000x reference)
#include <cuda_runtime.h>
#include <cuda_bf16.h>
#include <cuda_fp16.h>
#include <cuda_fp8.h>
#include <math.h>
#include <float.h>
#include <stdint.h>

// ---------------------------------------------------------------------------
// VectorQuantizer: z[32,4096,64] fp32, codebook[1024,64] fp32
// Output (concat float32): quantized[8388608], loss, indices[131072],
//   codebook_loss, commitment_loss, perplexity, usage[1024], soft_usage[1024]
//
// FUSED k1+k2: per CTA (64 rows), phase 1 runs the 1-term fp16 m16n8k16
// distance GEMM writing fp8(d - chunk_min) into SMEM (never DRAM); phase 2
// (warp-local: same warp, same rows) does softmax/soft_usage + exact-fp32
// argmin refine + quantized gather/store + mse from SMEM.
// ---------------------------------------------------------------------------

#define N_ROWS 131072
#define DIM    64
#define NCODES 1024
#define MT     64          // rows per CTA (4 warps x 16 rows)
#define THR1   128
#define NCHUNK 16
#define RS     260         // scratch row stride in u32 (256 + 4 pad: bank-safe)
#define L2E    1.4426950408889634f
#define CANDF  0.8352702f   /* exp(-0.18): window covers GEMM + fp8 error */

#define OFF_Q     0
#define OFF_LOSS  8388608
#define OFF_IDX   8388609
#define OFF_CBL   8519681
#define OFF_CML   8519682
#define OFF_PERP  8519683
#define OFF_USAGE 8519684
#define OFF_SOFT  8520708

// Dynamic SMEM layout (u32 offsets):
//   Bs    [3][2048]      @ 0      (B ring, 24 KB)
//   cc_s  [1024] float   @ 6144   (phase 1)  -- ALIASED as soft_s in phase 2
//   stg   [4][288] u16   @ 7168   (576 u32)
//   mch_s [64][16] float @ 7744
//   dsc   [64][RS] u32   @ 8768   (fp8 scratch, 65 KB)
#define SM_BS    0
#define SM_CC    6144
#define SM_STG   7168
#define SM_MCH   7744
#define SM_DSC   8768
#define SM_WORDS 25408      // 101632 bytes

// Device globals (accumulators only; no big scratch anymore).
__device__ uint32_t g_cbh[32 * NCODES];             // fp16x2, MMA-fragment order
__device__ float    g_cc[NCODES];
__device__ float    g_soft[NCODES];
__device__ float    g_counts[NCODES];
__device__ float    g_sq;

// ---------------- helpers ---------------------------------------------------
__device__ __forceinline__ uint32_t smem_u32(const void* p) {
    uint32_t a;
    asm("{ .reg .u64 t; cvta.to.shared.u64 t, %1; cvt.u32.u64 %0, t; }"
        : "=r"(a) : "l"(p));
    return a;
}
__device__ __forceinline__ void cp16(uint32_t dst, const void* src) {
    asm volatile("cp.async.cg.shared.global [%0], [%1], 16;"
                 :: "r"(dst), "l"(src) : "memory");
}
#define CP_COMMIT() asm volatile("cp.async.commit_group;" ::: "memory")
#define CP_WAIT1()  asm volatile("cp.async.wait_group 1;" ::: "memory")

__device__ __forceinline__ uint32_t pk_f16x2(float a, float b) {
    __half2 h = __floats2half2_rn(a, b);
    return *reinterpret_cast<uint32_t*>(&h);
}
__device__ __forceinline__ unsigned short pk_f8x2(float a, float b) {
    return __nv_cvt_float2_to_fp8x2(make_float2(a, b), __NV_SATFINITE, __NV_E4M3);
}

#define MMAH(d, a, b0_, b1_) \
    asm volatile("mma.sync.aligned.m16n8k16.row.col.f32.f16.f16.f32 " \
        "{%0,%1,%2,%3}, {%4,%5,%6,%7}, {%8,%9}, {%0,%1,%2,%3};" \
        : "+f"((d)[0]), "+f"((d)[1]), "+f"((d)[2]), "+f"((d)[3]) \
        : "r"((a)[0]), "r"((a)[1]), "r"((a)[2]), "r"((a)[3]), \
          "r"(b0_), "r"(b1_))

// ---------------------------------------------------------------------------
// k0: codebook -> MMA-fragment-ordered fp16x2 + cc + zero accumulators.
// ---------------------------------------------------------------------------
__global__ void k0_init(const float* __restrict__ cbk) {
    const int c = blockIdx.x * 256 + threadIdx.x;   // code 0..1023
    float x[64];
    const float4* p = reinterpret_cast<const float4*>(cbk + (size_t)c * DIM);
    float cs = 0.f;
#pragma unroll
    for (int i = 0; i < 16; i++) {
        float4 v = p[i];
        x[4*i+0] = v.x; x[4*i+1] = v.y; x[4*i+2] = v.z; x[4*i+3] = v.w;
        cs = fmaf(v.x, v.x, fmaf(v.y, v.y, fmaf(v.z, v.z, fmaf(v.w, v.w, cs))));
    }
    const int ch = c >> 6, nloc = c & 63;
    const int nl = nloc & 7, s = nloc >> 3;
    const int shalf = s >> 2, j = s & 3;
#pragma unroll
    for (int k2 = 0; k2 < 32; k2++) {
        const int kc = k2 >> 3, within = k2 & 7;
        const int q = within & 3, khalf = within >> 2;
        const int l = nl * 4 + q;
        const int g = khalf * 2 + shalf;
        const int idx = ch * 2048 + kc * 512 + g * 128 + l * 4 + j;
        g_cbh[idx] = pk_f16x2(x[2*k2], x[2*k2+1]);
    }
    g_cc[c] = cs;
    g_soft[c] = 0.f;
    g_counts[c] = 0.f;
    if (c == 0) g_sq = 0.f;
}

// ---------------------------------------------------------------------------
// k_fused: GEMM (phase 1) + softmax/argmin/gather (phase 2), scratch in SMEM.
// grid = 2048 x 128 thr (4 warps), 2 CTAs/SM (101.6 KB dynamic smem each).
// ---------------------------------------------------------------------------
__global__ void __launch_bounds__(THR1, 2) k_fused(const float* __restrict__ z,
                                                   const float* __restrict__ cbk,
                                                   float* __restrict__ out) {
    extern __shared__ uint32_t sm[];
    uint32_t* Bs   = sm + SM_BS;                      // [3][2048]
    float*    cc_s = reinterpret_cast<float*>(sm + SM_CC);
    unsigned short* stg = reinterpret_cast<unsigned short*>(sm + SM_STG);
    float*    mch_s = reinterpret_cast<float*>(sm + SM_MCH);
    uint32_t* dsc  = sm + SM_DSC;                     // [64][RS]
    __shared__ float ws[4];

    const int tid = threadIdx.x;
    const int w = tid >> 5, l = tid & 31, q = l & 3, nl = l >> 2;
    const int row0 = blockIdx.x * MT;

    // ---------------- phase 1: distance GEMM -> SMEM fp8 scratch ----------
    // prefetch chunk 0 -> Bs[0], chunk 1 -> Bs[1]
#pragma unroll
    for (int p = 0; p < 2; p++) {
#pragma unroll
        for (int i = 0; i < 4; i++) {
            const int id = tid + i * THR1;
            cp16(smem_u32(&Bs[(size_t)p * 2048 + id * 4]), g_cbh + p * 2048 + id * 4);
        }
        CP_COMMIT();
    }
#pragma unroll
    for (int p = 0; p < 2; p++) {
        const int i4 = tid + p * THR1;
        *reinterpret_cast<float4*>(&cc_s[i4 * 4]) =
            *reinterpret_cast<const float4*>(g_cc + i4 * 4);
    }

    // A fragments (fp16) directly from global + per-row zz
    uint32_t Ah[16];
    float zz0 = 0.f, zz1 = 0.f;
    const int r0 = row0 + w * 16 + nl, r1 = r0 + 8;
#pragma unroll
    for (int kc = 0; kc < 4; kc++) {
        const int k = kc * 16 + 2 * q;
        float2 v0 = *reinterpret_cast<const float2*>(z + (size_t)r0 * DIM + k);
        float2 v1 = *reinterpret_cast<const float2*>(z + (size_t)r1 * DIM + k);
        float2 v2 = *reinterpret_cast<const float2*>(z + (size_t)r0 * DIM + k + 8);
        float2 v3 = *reinterpret_cast<const float2*>(z + (size_t)r1 * DIM + k + 8);
        zz0 = fmaf(v0.x, v0.x, fmaf(v0.y, v0.y, fmaf(v2.x, v2.x, fmaf(v2.y, v2.y, zz0))));
        zz1 = fmaf(v1.x, v1.x, fmaf(v1.y, v1.y, fmaf(v3.x, v3.x, fmaf(v3.y, v3.y, zz1))));
        Ah[kc * 4 + 0] = pk_f16x2(v0.x, v0.y);
        Ah[kc * 4 + 1] = pk_f16x2(v1.x, v1.y);
        Ah[kc * 4 + 2] = pk_f16x2(v2.x, v2.y);
        Ah[kc * 4 + 3] = pk_f16x2(v3.x, v3.y);
    }
    zz0 += __shfl_xor_sync(0xFFFFFFFFu, zz0, 1);
    zz0 += __shfl_xor_sync(0xFFFFFFFFu, zz0, 2);
    zz1 += __shfl_xor_sync(0xFFFFFFFFu, zz1, 1);
    zz1 += __shfl_xor_sync(0xFFFFFFFFu, zz1, 2);

#pragma unroll 1
    for (int ch = 0; ch < NCHUNK; ch++) {
        CP_WAIT1();
        __syncthreads();

        if (ch < NCHUNK - 2) {
            const int n0 = (ch + 2) * 2048;
            const int pb = (ch + 2) % 3;
#pragma unroll
            for (int i = 0; i < 4; i++) {
                const int id = tid + i * THR1;
                cp16(smem_u32(&Bs[(size_t)pb * 2048 + id * 4]), g_cbh + n0 + id * 4);
            }
        }
        CP_COMMIT();

        const uint32_t* BH = Bs + (size_t)(ch % 3) * 2048;

        float acc[32];
#pragma unroll
        for (int i = 0; i < 32; i++) acc[i] = 0.f;

#pragma unroll
        for (int kc = 0; kc < 4; kc++) {
            const uint32_t* ah = &Ah[kc * 4];
            const uint32_t* bp = BH + kc * 512 + l * 4;
            uint4 b00 = *reinterpret_cast<const uint4*>(bp);
            uint4 b01 = *reinterpret_cast<const uint4*>(bp + 128);
            uint4 b10 = *reinterpret_cast<const uint4*>(bp + 256);
            uint4 b11 = *reinterpret_cast<const uint4*>(bp + 384);
            uint32_t bh0[8] = {b00.x, b00.y, b00.z, b00.w, b01.x, b01.y, b01.z, b01.w};
            uint32_t bh1[8] = {b10.x, b10.y, b10.z, b10.w, b11.x, b11.y, b11.z, b11.w};
#pragma unroll
            for (int s = 0; s < 8; s++)
                MMAH(&acc[s * 4], ah, bh0[s], bh1[s]);
        }

        // epilogue: d = zz + cc - 2*dot; chunk mins
        float m0 = FLT_MAX, m1 = FLT_MAX;
#pragma unroll
        for (int s = 0; s < 8; s++) {
            float2 cv = *reinterpret_cast<const float2*>(&cc_s[ch * 64 + s * 8 + 2 * q]);
            acc[s*4+0] = fmaf(-2.f, acc[s*4+0], zz0 + cv.x);
            acc[s*4+1] = fmaf(-2.f, acc[s*4+1], zz0 + cv.y);
            acc[s*4+2] = fmaf(-2.f, acc[s*4+2], zz1 + cv.x);
            acc[s*4+3] = fmaf(-2.f, acc[s*4+3], zz1 + cv.y);
            m0 = fminf(m0, fminf(acc[s*4+0], acc[s*4+1]));
            m1 = fminf(m1, fminf(acc[s*4+2], acc[s*4+3]));
        }
        m0 = fminf(m0, __shfl_xor_sync(0xFFFFFFFFu, m0, 1));
        m0 = fminf(m0, __shfl_xor_sync(0xFFFFFFFFu, m0, 2));
        m1 = fminf(m1, __shfl_xor_sync(0xFFFFFFFFu, m1, 1));
        m1 = fminf(m1, __shfl_xor_sync(0xFFFFFFFFu, m1, 2));
        const int rl0 = w * 16 + nl, rl1 = rl0 + 8;
        if (q == 0) {
            mch_s[rl0 * 16 + ch] = m0;
            mch_s[rl1 * 16 + ch] = m1;
        }

        unsigned short f0[8], f1[8];
#pragma unroll
        for (int s = 0; s < 8; s++) {
            f0[s] = pk_f8x2(acc[s*4+0] - m0, acc[s*4+1] - m0);
            f1[s] = pk_f8x2(acc[s*4+2] - m1, acc[s*4+3] - m1);
        }

        unsigned short* sw = stg + w * 288;
#pragma unroll
        for (int s = 0; s < 8; s++) sw[nl * 36 + 4 * s + q] = f0[s];
        __syncwarp();
        {
            const int b = l & 3, r = l >> 2;
            uint2 v0 = *reinterpret_cast<const uint2*>(&sw[r * 36 + 8 * b]);
            uint2 v1 = *reinterpret_cast<const uint2*>(&sw[r * 36 + 8 * b + 4]);
            uint32_t* dst = dsc + (w * 16 + r) * RS + ch * 16 + 4 * b;
            *reinterpret_cast<uint2*>(dst) = v0;
            *reinterpret_cast<uint2*>(dst + 2) = v1;
        }
        __syncwarp();
#pragma unroll
        for (int s = 0; s < 8; s++) sw[nl * 36 + 4 * s + q] = f1[s];
        __syncwarp();
        {
            const int b = l & 3, r = l >> 2;
            uint2 v0 = *reinterpret_cast<const uint2*>(&sw[r * 36 + 8 * b]);
            uint2 v1 = *reinterpret_cast<const uint2*>(&sw[r * 36 + 8 * b + 4]);
            uint32_t* dst = dsc + (w * 16 + 8 + r) * RS + ch * 16 + 4 * b;
            *reinterpret_cast<uint2*>(dst) = v0;
            *reinterpret_cast<uint2*>(dst + 2) = v1;
        }
        __syncwarp();
    }

    // ---------------- phase transition: cc_s becomes soft_s ----------------
    __syncthreads();
    float* soft_s = cc_s;                  // alias (cc no longer needed)
    for (int i = tid; i < NCODES; i += THR1) soft_s[i] = 0.f;
    __syncthreads();

    // ---------------- phase 2: softmax + argmin + gather (warp-local) ------
    float soft_acc[32];
#pragma unroll
    for (int i = 0; i < 32; i++) soft_acc[i] = 0.f;
    float sq_acc = 0.f;

#pragma unroll 1
    for (int rr = 0; rr < 16; rr++) {
        const int rloc = w * 16 + rr;
        const int row = row0 + rloc;

        float mch = (l < NCHUNK) ? mch_s[rloc * 16 + l] : FLT_MAX;
        float m = mch;
#pragma unroll
        for (int o = 16; o > 0; o >>= 1) m = fminf(m, __shfl_xor_sync(0xFFFFFFFFu, m, o));
        const float bias = (m - mch) * L2E;

        const float2 zrow = *reinterpret_cast<const float2*>(z + (size_t)row * DIM + 2 * l);
        const uint32_t* rp = dsc + rloc * RS;

        float e[32];
        float Z = 0.f, lemax = 0.f;
#pragma unroll
        for (int t = 0; t < 4; t++) {
            uint2 uq = *reinterpret_cast<const uint2*>(rp + 64 * t + 2 * l);
            float b = __shfl_sync(0xFFFFFFFFu, bias, 4 * t + (l >> 3));
            uint32_t us[2] = {uq.x, uq.y};
#pragma unroll
            for (int p = 0; p < 2; p++) {
                __half2_raw h0r = __nv_cvt_fp8x2_to_halfraw2(
                    (__nv_fp8x2_storage_t)(us[p] & 0xFFFFu), __NV_E4M3);
                __half2_raw h1r = __nv_cvt_fp8x2_to_halfraw2(
                    (__nv_fp8x2_storage_t)(us[p] >> 16), __NV_E4M3);
                float2 d0 = __half22float2(*reinterpret_cast<__half2*>(&h0r));
                float2 d1 = __half22float2(*reinterpret_cast<__half2*>(&h1r));
                float a0 = fmaf(-d0.x, L2E, b);
                float a1 = fmaf(-d0.y, L2E, b);
                float a2 = fmaf(-d1.x, L2E, b);
                float a3 = fmaf(-d1.y, L2E, b);
                __half2 e01 = h2exp2(__floats2half2_rn(a0, a1));
                __half2 e23 = h2exp2(__floats2half2_rn(a2, a3));
                float2 ef0 = __half22float2(e01);
                float2 ef1 = __half22float2(e23);
                const int ib = t * 8 + p * 4;
                e[ib + 0] = ef0.x; e[ib + 1] = ef0.y;
                e[ib + 2] = ef1.x; e[ib + 3] = ef1.y;
                Z += ef0.x + ef0.y + ef1.x + ef1.y;
                lemax = fmaxf(lemax, fmaxf(fmaxf(ef0.x, ef0.y), fmaxf(ef1.x, ef1.y)));
            }
        }
        float emax = lemax;
#pragma unroll
        for (int o = 16; o > 0; o >>= 1) {
            Z += __shfl_xor_sync(0xFFFFFFFFu, Z, o);
            emax = fmaxf(emax, __shfl_xor_sync(0xFFFFFFFFu, emax, o));
        }
        const float invZ = __fdividef(1.f, Z);
#pragma unroll
        for (int i = 0; i < 32; i++) soft_acc[i] = fmaf(e[i], invZ, soft_acc[i]);

        // exact refine over candidates (e[i] of lane src -> col = 8*src + 256*(i>>3) + (i&7))
        const float thr = emax * CANDF;
        float bd = FLT_MAX;
        int bc = 0x7FFFFFFF;
        unsigned bal = __ballot_sync(0xFFFFFFFFu, lemax >= thr);
        while (bal) {
            const int src = __ffs(bal) - 1;
            bal &= bal - 1;
#pragma unroll
            for (int jj = 0; jj < 32; jj++) {
                float ev = __shfl_sync(0xFFFFFFFFu, e[jj], src);
                if (ev >= thr) {
                    const int col = 8 * src + 256 * (jj >> 3) + (jj & 7);
                    float2 cv = *reinterpret_cast<const float2*>(
                        cbk + (size_t)col * DIM + 2 * l);
                    float s = fmaf(cv.x, cv.x, cv.y * cv.y)
                            - 2.f * fmaf(zrow.x, cv.x, zrow.y * cv.y);
#pragma unroll
                    for (int o = 16; o > 0; o >>= 1)
                        s += __shfl_xor_sync(0xFFFFFFFFu, s, o);
                    if (s < bd || (s == bd && col < bc)) { bd = s; bc = col; }
                }
            }
        }

        // fused: quantized gather + store + mse
        float2 cq = *reinterpret_cast<const float2*>(cbk + (size_t)bc * DIM + 2 * l);
        *reinterpret_cast<float2*>(out + OFF_Q + (size_t)row * DIM + 2 * l) = cq;
        float dx = cq.x - zrow.x, dy = cq.y - zrow.y;
        sq_acc = fmaf(dx, dx, fmaf(dy, dy, sq_acc));

        if (l == 0) {
            out[OFF_IDX + row] = (float)bc;
            atomicAdd(&g_counts[bc], 1.f);
        }
    }

#pragma unroll
    for (int jj = 0; jj < 32; jj++)
        atomicAdd(&soft_s[8 * l + 256 * (jj >> 3) + (jj & 7)], soft_acc[jj]);

#pragma unroll
    for (int o = 16; o > 0; o >>= 1) sq_acc += __shfl_xor_sync(0xFFFFFFFFu, sq_acc, o);
    if (l == 0) ws[w] = sq_acc;
    __syncthreads();
    if (tid == 0) {
        float tt = ws[0] + ws[1] + ws[2] + ws[3];
        atomicAdd(&g_sq, tt);
    }
    for (int i = tid; i < NCODES; i += THR1) atomicAdd(&g_soft[i], soft_s[i]);
}

// ---------------------------------------------------------------------------
// k4: finalize scalars, usage, soft_usage, perplexity.
// ---------------------------------------------------------------------------
__global__ void __launch_bounds__(1024) k4_fin(float* __restrict__ out) {
    const int c = threadIdx.x;
    const float invN = 1.f / (float)N_ROWS;

    float usage = g_counts[c] * invN;
    out[OFF_USAGE + c] = usage;
    out[OFF_SOFT + c]  = g_soft[c] * invN;

    float term = usage * logf(usage + 1e-8f);
#pragma unroll
    for (int o = 16; o > 0; o >>= 1) term += __shfl_xor_sync(0xFFFFFFFFu, term, o);

    __shared__ float red[32];
    if ((c & 31) == 0) red[c >> 5] = term;
    __syncthreads();
    if (c == 0) {
        float sum = 0.f;
#pragma unroll
        for (int i = 0; i < 32; i++) sum += red[i];
        float mse = g_sq / (float)((size_t)N_ROWS * DIM);
        out[OFF_LOSS] = mse * 1.25f;
        out[OFF_CBL]  = mse;
        out[OFF_CML]  = mse;
        out[OFF_PERP] = expf(-sum);
    }
}

// ---------------------------------------------------------------------------
extern "C" void kernel_launch(void* const* d_in, const int* in_sizes, int n_in,
                              void* d_out, int out_size) {
    const float* z   = (const float*)d_in[0];
    const float* cbk = (const float*)d_in[1];
    float* out = (float*)d_out;
    (void)in_sizes; (void)n_in; (void)out_size;

    cudaFuncSetAttribute(k_fused, cudaFuncAttributeMaxDynamicSharedMemorySize,
                         SM_WORDS * 4);

    k0_init<<<4, 256>>>(cbk);
    k_fused<<<N_ROWS / MT, THR1, SM_WORDS * 4>>>(z, cbk, out);
    k4_fin<<<1, 1024>>>(out);
}

// round 17
// speedup vs baseline: 1.7723x; 1.7723x over previous
#include <cuda_runtime.h>
#include <cuda_bf16.h>
#include <cuda_fp16.h>
#include <cuda_fp8.h>
#include <math.h>
#include <float.h>
#include <stdint.h>

// ---------------------------------------------------------------------------
// VectorQuantizer: z[32,4096,64] fp32, codebook[1024,64] fp32
// Output (concat float32): quantized[8388608], loss, indices[131072],
//   codebook_loss, commitment_loss, perplexity, usage[1024], soft_usage[1024]
//
// k1: 1-term fp16 m16n8k16 distance GEMM; codebook pre-permuted into MMA
//     fragment order -> B loads are 4x LDS.128 per kc (conflict-free).
//     Scratch: fp8 e4m3 of (d - chunk_min).
// k2: softmax/soft_usage from fp8 scratch + argmin (single-candidate fast
//     path; exact-fp32 refine only on multi-candidate rows) + fused
//     quantized gather/store + mse.
// ---------------------------------------------------------------------------

#define N_ROWS 131072
#define DIM    64
#define NCODES 1024
#define MT     64          // rows per CTA (4 warps x 16 rows)
#define THR1   128
#define NCHUNK 16
#define L2E    1.4426950408889634f
#define CANDF  0.8352702f   /* exp(-0.18): window covers GEMM + fp8 error */

#define OFF_Q     0
#define OFF_LOSS  8388608
#define OFF_IDX   8388609
#define OFF_CBL   8519681
#define OFF_CML   8519682
#define OFF_PERP  8519683
#define OFF_USAGE 8519684
#define OFF_SOFT  8520708

// Scratch (device globals; no allocations allowed).
__device__ uint32_t g_df8[(size_t)N_ROWS * 256];    // 128 MB: fp8 e4m3 of (d - mch)
__device__ float    g_mch[(size_t)N_ROWS * NCHUNK]; // per-row per-chunk mins
__device__ uint32_t g_cbh[32 * NCODES];             // fp16x2, MMA-fragment order
__device__ float    g_cc[NCODES];
__device__ float    g_soft[NCODES];
__device__ float    g_counts[NCODES];
__device__ float    g_sq;

// ---------------- helpers ---------------------------------------------------
__device__ __forceinline__ uint32_t smem_u32(const void* p) {
    uint32_t a;
    asm("{ .reg .u64 t; cvta.to.shared.u64 t, %1; cvt.u32.u64 %0, t; }"
        : "=r"(a) : "l"(p));
    return a;
}
__device__ __forceinline__ void cp16(uint32_t dst, const void* src) {
    asm volatile("cp.async.cg.shared.global [%0], [%1], 16;"
                 :: "r"(dst), "l"(src) : "memory");
}
#define CP_COMMIT() asm volatile("cp.async.commit_group;" ::: "memory")
#define CP_WAIT1()  asm volatile("cp.async.wait_group 1;" ::: "memory")

__device__ __forceinline__ uint32_t pk_f16x2(float a, float b) {
    __half2 h = __floats2half2_rn(a, b);
    return *reinterpret_cast<uint32_t*>(&h);
}
__device__ __forceinline__ unsigned short pk_f8x2(float a, float b) {
    return __nv_cvt_float2_to_fp8x2(make_float2(a, b), __NV_SATFINITE, __NV_E4M3);
}

#define MMAH(d, a, b0_, b1_) \
    asm volatile("mma.sync.aligned.m16n8k16.row.col.f32.f16.f16.f32 " \
        "{%0,%1,%2,%3}, {%4,%5,%6,%7}, {%8,%9}, {%0,%1,%2,%3};" \
        : "+f"((d)[0]), "+f"((d)[1]), "+f"((d)[2]), "+f"((d)[3]) \
        : "r"((a)[0]), "r"((a)[1]), "r"((a)[2]), "r"((a)[3]), \
          "r"(b0_), "r"(b1_))

// ---------------------------------------------------------------------------
// k0: codebook -> MMA-fragment-ordered fp16x2 + cc + zero accumulators.
// ---------------------------------------------------------------------------
__global__ void k0_init(const float* __restrict__ cbk) {
    const int c = blockIdx.x * 256 + threadIdx.x;   // code 0..1023
    float x[64];
    const float4* p = reinterpret_cast<const float4*>(cbk + (size_t)c * DIM);
    float cs = 0.f;
#pragma unroll
    for (int i = 0; i < 16; i++) {
        float4 v = p[i];
        x[4*i+0] = v.x; x[4*i+1] = v.y; x[4*i+2] = v.z; x[4*i+3] = v.w;
        cs = fmaf(v.x, v.x, fmaf(v.y, v.y, fmaf(v.z, v.z, fmaf(v.w, v.w, cs))));
    }
    const int ch = c >> 6, nloc = c & 63;
    const int nl = nloc & 7, s = nloc >> 3;        // s = 0..7
    const int shalf = s >> 2, j = s & 3;
#pragma unroll
    for (int k2 = 0; k2 < 32; k2++) {
        const int kc = k2 >> 3, within = k2 & 7;
        const int q = within & 3, khalf = within >> 2;
        const int l = nl * 4 + q;
        const int g = khalf * 2 + shalf;
        const int idx = ch * 2048 + kc * 512 + g * 128 + l * 4 + j;
        g_cbh[idx] = pk_f16x2(x[2*k2], x[2*k2+1]);
    }
    g_cc[c] = cs;
    g_soft[c] = 0.f;
    g_counts[c] = 0.f;
    if (c == 0) g_sq = 0.f;
}

// ---------------------------------------------------------------------------
// k1: 1-term fp16 distance GEMM.  grid = 2048 x 128 thr (4 warps, 5 CTAs/SM).
//     3-stage cp.async ring; B via fragment-ordered LDS.128 (4 per kc).
//     Scratch: fp8 of (d - chunk_min), staged via warp smem -> STG.64 x2.
// ---------------------------------------------------------------------------
__global__ void __launch_bounds__(THR1, 5) k1_gemm(const float* __restrict__ z) {
    __shared__ __align__(16) uint32_t Bs[3][2048];   // B ring (24 KB)
    __shared__ float cc_s[NCODES];                   // 4 KB
    __shared__ __align__(8) unsigned short stg16[4][288];  // warp staging

    const int tid = threadIdx.x;
    const int w = tid >> 5, l = tid & 31, q = l & 3, nl = l >> 2;
    const int row0 = blockIdx.x * MT;

    // prefetch chunk 0 -> Bs[0], chunk 1 -> Bs[1]
#pragma unroll
    for (int p = 0; p < 2; p++) {
#pragma unroll
        for (int i = 0; i < 4; i++) {
            const int id = tid + i * THR1;
            cp16(smem_u32(&Bs[p][id * 4]), g_cbh + p * 2048 + id * 4);
        }
        CP_COMMIT();
    }
#pragma unroll
    for (int p = 0; p < 2; p++) {
        const int i4 = tid + p * THR1;
        *reinterpret_cast<float4*>(&cc_s[i4 * 4]) =
            *reinterpret_cast<const float4*>(g_cc + i4 * 4);
    }

    // A fragments (fp16) directly from global + per-row zz
    uint32_t Ah[16];
    float zz0 = 0.f, zz1 = 0.f;
    const int r0 = row0 + w * 16 + nl, r1 = r0 + 8;
#pragma unroll
    for (int kc = 0; kc < 4; kc++) {
        const int k = kc * 16 + 2 * q;
        float2 v0 = *reinterpret_cast<const float2*>(z + (size_t)r0 * DIM + k);
        float2 v1 = *reinterpret_cast<const float2*>(z + (size_t)r1 * DIM + k);
        float2 v2 = *reinterpret_cast<const float2*>(z + (size_t)r0 * DIM + k + 8);
        float2 v3 = *reinterpret_cast<const float2*>(z + (size_t)r1 * DIM + k + 8);
        zz0 = fmaf(v0.x, v0.x, fmaf(v0.y, v0.y, fmaf(v2.x, v2.x, fmaf(v2.y, v2.y, zz0))));
        zz1 = fmaf(v1.x, v1.x, fmaf(v1.y, v1.y, fmaf(v3.x, v3.x, fmaf(v3.y, v3.y, zz1))));
        Ah[kc * 4 + 0] = pk_f16x2(v0.x, v0.y);
        Ah[kc * 4 + 1] = pk_f16x2(v1.x, v1.y);
        Ah[kc * 4 + 2] = pk_f16x2(v2.x, v2.y);
        Ah[kc * 4 + 3] = pk_f16x2(v3.x, v3.y);
    }
    zz0 += __shfl_xor_sync(0xFFFFFFFFu, zz0, 1);
    zz0 += __shfl_xor_sync(0xFFFFFFFFu, zz0, 2);
    zz1 += __shfl_xor_sync(0xFFFFFFFFu, zz1, 1);
    zz1 += __shfl_xor_sync(0xFFFFFFFFu, zz1, 2);

#pragma unroll 1
    for (int ch = 0; ch < NCHUNK; ch++) {
        CP_WAIT1();
        __syncthreads();   // buf ch%3 ready AND all warps done reading buf (ch-1)%3

        // prefetch chunk ch+2 into buf (ch+2)%3 == (ch-1)%3 (safe: see sync above)
        if (ch < NCHUNK - 2) {
            const int n0 = (ch + 2) * 2048;
            const int pb = (ch + 2) % 3;
#pragma unroll
            for (int i = 0; i < 4; i++) {
                const int id = tid + i * THR1;
                cp16(smem_u32(&Bs[pb][id * 4]), g_cbh + n0 + id * 4);
            }
        }
        CP_COMMIT();

        const uint32_t* BH = Bs[ch % 3];

        float acc[32];
#pragma unroll
        for (int i = 0; i < 32; i++) acc[i] = 0.f;

#pragma unroll
        for (int kc = 0; kc < 4; kc++) {
            const uint32_t* ah = &Ah[kc * 4];
            const uint32_t* bp = BH + kc * 512 + l * 4;
            // conflict-free LDS.128: 8 lanes/phase span all 32 banks
            uint4 b00 = *reinterpret_cast<const uint4*>(bp);          // b0 s0..3
            uint4 b01 = *reinterpret_cast<const uint4*>(bp + 128);    // b0 s4..7
            uint4 b10 = *reinterpret_cast<const uint4*>(bp + 256);    // b1 s0..3
            uint4 b11 = *reinterpret_cast<const uint4*>(bp + 384);    // b1 s4..7
            uint32_t bh0[8] = {b00.x, b00.y, b00.z, b00.w, b01.x, b01.y, b01.z, b01.w};
            uint32_t bh1[8] = {b10.x, b10.y, b10.z, b10.w, b11.x, b11.y, b11.z, b11.w};
#pragma unroll
            for (int s = 0; s < 8; s++)
                MMAH(&acc[s * 4], ah, bh0[s], bh1[s]);
        }

        // epilogue: d = zz + cc - 2*dot; chunk mins
        float m0 = FLT_MAX, m1 = FLT_MAX;
#pragma unroll
        for (int s = 0; s < 8; s++) {
            float2 cv = *reinterpret_cast<const float2*>(&cc_s[ch * 64 + s * 8 + 2 * q]);
            acc[s*4+0] = fmaf(-2.f, acc[s*4+0], zz0 + cv.x);
            acc[s*4+1] = fmaf(-2.f, acc[s*4+1], zz0 + cv.y);
            acc[s*4+2] = fmaf(-2.f, acc[s*4+2], zz1 + cv.x);
            acc[s*4+3] = fmaf(-2.f, acc[s*4+3], zz1 + cv.y);
            m0 = fminf(m0, fminf(acc[s*4+0], acc[s*4+1]));
            m1 = fminf(m1, fminf(acc[s*4+2], acc[s*4+3]));
        }
        m0 = fminf(m0, __shfl_xor_sync(0xFFFFFFFFu, m0, 1));
        m0 = fminf(m0, __shfl_xor_sync(0xFFFFFFFFu, m0, 2));
        m1 = fminf(m1, __shfl_xor_sync(0xFFFFFFFFu, m1, 1));
        m1 = fminf(m1, __shfl_xor_sync(0xFFFFFFFFu, m1, 2));
        if (q == 0) {
            g_mch[(size_t)r0 * NCHUNK + ch] = m0;
            g_mch[(size_t)r1 * NCHUNK + ch] = m1;
        }

        // pack fp8x2(d - min): pair index within row-chunk = 4s + q
        unsigned short f0[8], f1[8];
#pragma unroll
        for (int s = 0; s < 8; s++) {
            f0[s] = pk_f8x2(acc[s*4+0] - m0, acc[s*4+1] - m0);
            f1[s] = pk_f8x2(acc[s*4+2] - m1, acc[s*4+3] - m1);
        }

        // staged coalesced stores: r0 group (rows row0 + w*16 + 0..7)
#pragma unroll
        for (int s = 0; s < 8; s++) stg16[w][nl * 36 + 4 * s + q] = f0[s];
        __syncwarp();
        {
            const int b = l & 3, r = l >> 2;
            uint2 v0 = *reinterpret_cast<const uint2*>(&stg16[w][r * 36 + 8 * b]);
            uint2 v1 = *reinterpret_cast<const uint2*>(&stg16[w][r * 36 + 8 * b + 4]);
            uint32_t* dst = g_df8 + (size_t)(row0 + w * 16 + r) * 256
                          + ch * 16 + 4 * b;
            *reinterpret_cast<uint2*>(dst) = v0;
            *reinterpret_cast<uint2*>(dst + 2) = v1;
        }
        __syncwarp();
        // r1 group (rows +8)
#pragma unroll
        for (int s = 0; s < 8; s++) stg16[w][nl * 36 + 4 * s + q] = f1[s];
        __syncwarp();
        {
            const int b = l & 3, r = l >> 2;
            uint2 v0 = *reinterpret_cast<const uint2*>(&stg16[w][r * 36 + 8 * b]);
            uint2 v1 = *reinterpret_cast<const uint2*>(&stg16[w][r * 36 + 8 * b + 4]);
            uint32_t* dst = g_df8 + (size_t)(row0 + w * 16 + 8 + r) * 256
                          + ch * 16 + 4 * b;
            *reinterpret_cast<uint2*>(dst) = v0;
            *reinterpret_cast<uint2*>(dst + 2) = v1;
        }
        __syncwarp();
    }
}

// ---------------------------------------------------------------------------
// k2: Z + soft_usage (fp8 scratch, half2 ex2) + argmin (1-candidate fast path,
//     exact refine otherwise) + counts + indices + quantized gather/store +
//     mse.  warp-per-row, grid 1024 x 256.
// ---------------------------------------------------------------------------
__global__ void __launch_bounds__(256) k2_fuse(const float* __restrict__ z,
                                               const float* __restrict__ cbk,
                                               float* __restrict__ out) {
    __shared__ float soft_s[NCODES];
    __shared__ float ws[8];
    const int tid = threadIdx.x, w = tid >> 5, l = tid & 31;
    for (int i = tid; i < NCODES; i += 256) soft_s[i] = 0.f;
    __syncthreads();

    float soft_acc[32];
#pragma unroll
    for (int i = 0; i < 32; i++) soft_acc[i] = 0.f;
    float sq_acc = 0.f;

    const int rbase = blockIdx.x * 128 + w * 16;
#pragma unroll 1
    for (int rr = 0; rr < 16; rr++) {
        const int row = rbase + rr;

        // L2 prefetch of next row's 1KB scratch
        if (rr < 15) {
            const char* np = reinterpret_cast<const char*>(
                g_df8 + (size_t)(row + 1) * 256) + l * 16;
            asm volatile("prefetch.global.L2 [%0];" :: "l"(np));
            asm volatile("prefetch.global.L2 [%0];" :: "l"(np + 512));
        }

        float mch = (l < NCHUNK) ? g_mch[(size_t)row * NCHUNK + l] : FLT_MAX;
        float m = mch;
#pragma unroll
        for (int o = 16; o > 0; o >>= 1) m = fminf(m, __shfl_xor_sync(0xFFFFFFFFu, m, o));
        const float bias = (m - mch) * L2E;

        const uint2* rp = reinterpret_cast<const uint2*>(g_df8 + (size_t)row * 256);
        const float2 zrow = *reinterpret_cast<const float2*>(z + (size_t)row * DIM + 2 * l);

        float e[32];
        float Z = 0.f, lemax = 0.f;
#pragma unroll
        for (int t = 0; t < 4; t++) {
            uint2 uq = rp[32 * t + l];     // 8 fp8: codes 256t + 8l .. +7
            float b = __shfl_sync(0xFFFFFFFFu, bias, (256 * t + 8 * l) >> 6);
            uint32_t us[2] = {uq.x, uq.y};
#pragma unroll
            for (int p = 0; p < 2; p++) {
                __half2_raw h0r = __nv_cvt_fp8x2_to_halfraw2(
                    (__nv_fp8x2_storage_t)(us[p] & 0xFFFFu), __NV_E4M3);
                __half2_raw h1r = __nv_cvt_fp8x2_to_halfraw2(
                    (__nv_fp8x2_storage_t)(us[p] >> 16), __NV_E4M3);
                float2 d0 = __half22float2(*reinterpret_cast<__half2*>(&h0r));
                float2 d1 = __half22float2(*reinterpret_cast<__half2*>(&h1r));
                float a0 = fmaf(-d0.x, L2E, b);
                float a1 = fmaf(-d0.y, L2E, b);
                float a2 = fmaf(-d1.x, L2E, b);
                float a3 = fmaf(-d1.y, L2E, b);
                __half2 e01 = h2exp2(__floats2half2_rn(a0, a1));
                __half2 e23 = h2exp2(__floats2half2_rn(a2, a3));
                float2 ef0 = __half22float2(e01);
                float2 ef1 = __half22float2(e23);
                const int ib = t * 8 + p * 4;
                e[ib + 0] = ef0.x; e[ib + 1] = ef0.y;
                e[ib + 2] = ef1.x; e[ib + 3] = ef1.y;
                Z += ef0.x + ef0.y + ef1.x + ef1.y;
                lemax = fmaxf(lemax, fmaxf(fmaxf(ef0.x, ef0.y), fmaxf(ef1.x, ef1.y)));
            }
        }
        float emax = lemax;
#pragma unroll
        for (int o = 16; o > 0; o >>= 1) {
            Z += __shfl_xor_sync(0xFFFFFFFFu, Z, o);
            emax = fmaxf(emax, __shfl_xor_sync(0xFFFFFFFFu, emax, o));
        }
        const float invZ = __fdividef(1.f, Z);
#pragma unroll
        for (int i = 0; i < 32; i++) soft_acc[i] = fmaf(e[i], invZ, soft_acc[i]);

        // ---- argmin: single-candidate fast path, exact refine otherwise ----
        // e[i] of lane src -> col = 8*src + 256*(i>>3) + (i&7)
        const float thr = emax * CANDF;
        int cnt = 0, cidx = 0;
#pragma unroll
        for (int i = 0; i < 32; i++) {
            if (e[i] >= thr) { cnt++; cidx = i; }
        }
        const unsigned bal0 = __ballot_sync(0xFFFFFFFFu, cnt > 0);
        const int total = __reduce_add_sync(0xFFFFFFFFu, (unsigned)cnt);

        int bc;
        if (total == 1) {
            // the lone in-window candidate IS the argmin (window invariant)
            const int src = __ffs(bal0) - 1;
            const int jj = __shfl_sync(0xFFFFFFFFu, cidx, src);
            bc = 8 * src + 256 * (jj >> 3) + (jj & 7);
        } else {
            float bd = FLT_MAX;
            bc = 0x7FFFFFFF;
            unsigned bal = bal0;
            while (bal) {
                const int src = __ffs(bal) - 1;
                bal &= bal - 1;
#pragma unroll
                for (int jj = 0; jj < 32; jj++) {
                    float ev = __shfl_sync(0xFFFFFFFFu, e[jj], src);
                    if (ev >= thr) {
                        const int col = 8 * src + 256 * (jj >> 3) + (jj & 7);
                        float2 cv = *reinterpret_cast<const float2*>(
                            cbk + (size_t)col * DIM + 2 * l);
                        float s = fmaf(cv.x, cv.x, cv.y * cv.y)
                                - 2.f * fmaf(zrow.x, cv.x, zrow.y * cv.y);
#pragma unroll
                        for (int o = 16; o > 0; o >>= 1)
                            s += __shfl_xor_sync(0xFFFFFFFFu, s, o);
                        if (s < bd || (s == bd && col < bc)) { bd = s; bc = col; }
                    }
                }
            }
        }

        // fused: quantized gather + store + mse
        float2 cq = *reinterpret_cast<const float2*>(cbk + (size_t)bc * DIM + 2 * l);
        *reinterpret_cast<float2*>(out + OFF_Q + (size_t)row * DIM + 2 * l) = cq;
        float dx = cq.x - zrow.x, dy = cq.y - zrow.y;
        sq_acc = fmaf(dx, dx, fmaf(dy, dy, sq_acc));

        if (l == 0) {
            out[OFF_IDX + row] = (float)bc;
            atomicAdd(&g_counts[bc], 1.f);
        }
    }
#pragma unroll
    for (int jj = 0; jj < 32; jj++)
        atomicAdd(&soft_s[8 * l + 256 * (jj >> 3) + (jj & 7)], soft_acc[jj]);

#pragma unroll
    for (int o = 16; o > 0; o >>= 1) sq_acc += __shfl_xor_sync(0xFFFFFFFFu, sq_acc, o);
    if (l == 0) ws[w] = sq_acc;
    __syncthreads();
    if (tid == 0) {
        float tt = 0.f;
#pragma unroll
        for (int i = 0; i < 8; i++) tt += ws[i];
        atomicAdd(&g_sq, tt);
    }
    for (int i = tid; i < NCODES; i += 256) atomicAdd(&g_soft[i], soft_s[i]);
}

// ---------------------------------------------------------------------------
// k4: finalize scalars, usage, soft_usage, perplexity.
// ---------------------------------------------------------------------------
__global__ void __launch_bounds__(1024) k4_fin(float* __restrict__ out) {
    const int c = threadIdx.x;
    const float invN = 1.f / (float)N_ROWS;

    float usage = g_counts[c] * invN;
    out[OFF_USAGE + c] = usage;
    out[OFF_SOFT + c]  = g_soft[c] * invN;

    float term = usage * logf(usage + 1e-8f);
#pragma unroll
    for (int o = 16; o > 0; o >>= 1) term += __shfl_xor_sync(0xFFFFFFFFu, term, o);

    __shared__ float red[32];
    if ((c & 31) == 0) red[c >> 5] = term;
    __syncthreads();
    if (c == 0) {
        float sum = 0.f;
#pragma unroll
        for (int i = 0; i < 32; i++) sum += red[i];
        float mse = g_sq / (float)((size_t)N_ROWS * DIM);
        out[OFF_LOSS] = mse * 1.25f;
        out[OFF_CBL]  = mse;
        out[OFF_CML]  = mse;
        out[OFF_PERP] = expf(-sum);
    }
}

// ---------------------------------------------------------------------------
extern "C" void kernel_launch(void* const* d_in, const int* in_sizes, int n_in,
                              void* d_out, int out_size) {
    const float* z   = (const float*)d_in[0];
    const float* cbk = (const float*)d_in[1];
    float* out = (float*)d_out;
    (void)in_sizes; (void)n_in; (void)out_size;

    k0_init<<<4, 256>>>(cbk);
    k1_gemm<<<N_ROWS / MT, THR1>>>(z);
    k2_fuse<<<N_ROWS / 128, 256>>>(z, cbk, out);
    k4_fin<<<1, 1024>>>(out);
}